// round 2
// baseline (speedup 1.0000x reference)
#include <cuda_runtime.h>
#include <stdint.h>

#define NOPP 3
#define NS   80
#define NA   6
#define DD   512
#define BMAX 4096

// ---------------- device scratch (no allocations allowed) ----------------
__device__ float g_tbuf[NOPP * NS * BMAX * NA];   // t = -log(u) per gumbel draw (23.6 MB)
__device__ float g_einv[NOPP * BMAX * NA];        // exp(-logits[k,b,a])
__device__ float g_dist[NOPP * BMAX * NA];        // softmax(logits)
__device__ float g_base[BMAX * NA];               // x@W[:512] + b  (agent base logits)
__device__ float g_entpart[BMAX];                 // sum_k entropy(k,b)

// ---------------- kernel 1: fused GEMM (x @ [W_opp|W[:512]]) + softmax/entropy ----------------
#define K1_ROWS 16
__global__ void __launch_bounds__(768) k1(
    const float* __restrict__ x, const float* __restrict__ Wopp,
    const float* __restrict__ bopp, const float* __restrict__ W,
    const float* __restrict__ bias, float* __restrict__ out,
    int B, int out_size)
{
    __shared__ float xs[K1_ROWS * DD];       // 32 KB
    __shared__ float vals[K1_ROWS][25];      // 24 outputs per row (+pad)
    __shared__ float entkb[K1_ROWS][3];

    int tid  = threadIdx.x;
    int warp = tid >> 5;       // 0..23 -> output column o
    int lane = tid & 31;
    int b0   = blockIdx.x * K1_ROWS;

    // stage x rows
    for (int i = tid; i < K1_ROWS * DD; i += 768) {
        int r = i / DD;
        xs[i] = (b0 + r < B) ? x[(size_t)(b0 + r) * DD + (i % DD)] : 0.0f;
    }

    // each warp owns one output column o; W column in registers
    float wreg[16];
    int o = warp;
    if (o < 18) {
        int k = o / 6, a = o % 6;
#pragma unroll
        for (int j = 0; j < 16; j++)
            wreg[j] = Wopp[((size_t)k * DD + (lane + 32 * j)) * NA + a];
    } else {
        int a = o - 18;
#pragma unroll
        for (int j = 0; j < 16; j++)
            wreg[j] = W[(size_t)(lane + 32 * j) * NA + a];
    }
    __syncthreads();

    for (int r = 0; r < K1_ROWS; r++) {
        const float* xr = xs + r * DD;
        float acc = 0.0f;
#pragma unroll
        for (int j = 0; j < 16; j++)
            acc = fmaf(xr[lane + 32 * j], wreg[j], acc);
#pragma unroll
        for (int off = 16; off; off >>= 1)
            acc += __shfl_down_sync(0xffffffffu, acc, off);
        if (lane == 0) vals[r][o] = acc;
    }
    __syncthreads();

    // post-process: 48 (row, opponent) softmax tasks + 96 base tasks
    if (tid < K1_ROWS * 3) {
        int r = tid / 3, k = tid % 3;
        int b = b0 + r;
        if (b < B) {
            float l[NA], m = -1e30f;
#pragma unroll
            for (int a = 0; a < NA; a++) {
                l[a] = vals[r][k * 6 + a] + bopp[k * 6 + a];
                m = fmaxf(m, l[a]);
            }
            float e[NA], S = 0.0f;
#pragma unroll
            for (int a = 0; a < NA; a++) { e[a] = expf(l[a] - m); S += e[a]; }
            float logS = logf(S);
            float ent = 0.0f;
            int distoff = B * NA + (k * B + b) * NA;
#pragma unroll
            for (int a = 0; a < NA; a++) {
                float d = e[a] / S;
                g_dist[(k * B + b) * NA + a] = d;
                g_einv[(k * B + b) * NA + a] = expf(-l[a]);
                float lp = (l[a] - m) - logS;
                ent -= d * lp;
                if (out_size >= B * 24) out[distoff + a] = d;
            }
            entkb[r][k] = ent;
        } else entkb[r][k] = 0.0f;
    } else if (tid < K1_ROWS * 3 + K1_ROWS * 6) {
        int t2 = tid - K1_ROWS * 3;
        int r = t2 / 6, a = t2 % 6;
        int b = b0 + r;
        if (b < B) g_base[b * NA + a] = vals[r][18 + a] + bias[a];
    }
    __syncthreads();
    if (tid < K1_ROWS && b0 + tid < B)
        g_entpart[b0 + tid] = entkb[tid][0] + entkb[tid][1] + entkb[tid][2];
}

// ---------------- threefry2x32, key = (0, 42), counter = (hi=0, lo=i) ----------------
// jax partitionable stream, 32-bit draws: output = x0_final ^ x1_final (fold of
// the 64-bit hash), NOT the low word alone.
__device__ __forceinline__ uint32_t tf_fold(uint32_t c1)
{
    const uint32_t KS1 = 42u;
    const uint32_t KS2 = 0x1BD11BDAu ^ 42u;   // ks0 = 0
    uint32_t x0 = 0u, x1 = c1 + KS1;
#define TFR(r) { x0 += x1; x1 = __funnelshift_l(x1, x1, (r)); x1 ^= x0; }
    TFR(13) TFR(15) TFR(26) TFR(6)
    x0 += KS1; x1 += KS2 + 1u;
    TFR(17) TFR(29) TFR(16) TFR(24)
    x0 += KS2; x1 += 2u;                      // + ks0(=0) + 2
    TFR(13) TFR(15) TFR(26) TFR(6)
    /* x0 += ks0 (=0) */ x1 += KS1 + 3u;
    TFR(17) TFR(29) TFR(16) TFR(24)
    x0 += KS1; x1 += KS2 + 4u;
    TFR(13) TFR(15) TFR(26) TFR(6)
    x0 += KS2; x1 += 5u;                      // final injection (x0 now live!)
#undef TFR
    return x0 ^ x1;
}

__device__ __forceinline__ float bits_to_t(uint32_t bits)
{
    // jax uniform: u = (bitcast(bits>>9 | 0x3f800000) - 1) + tiny ; t = -log(u)
    float f = __uint_as_float((bits >> 9) | 0x3f800000u) - 1.0f;
    return -logf(f + 1.17549435e-38f);
}

__global__ void __launch_bounds__(256) k_rng(int total)
{
    int half = total >> 1;
    int i = blockIdx.x * 256 + threadIdx.x;
    if (i < half) {
        uint32_t b0 = tf_fold((uint32_t)i);            // 2 independent evals for ILP
        uint32_t b1 = tf_fold((uint32_t)(i + half));
        g_tbuf[i]        = bits_to_t(b0);
        g_tbuf[i + half] = bits_to_t(b1);
    }
}

// ---------------- kernel 3: sampling (argmin t*e^-logit) + weighted agent softmax ----------------
__global__ void __launch_bounds__(256) k3(const float* __restrict__ W,
                                          float* __restrict__ out, int B)
{
    __shared__ float W2s[18 * NA];
    int tid = threadIdx.x;
    if (tid < 18 * NA) W2s[tid] = W[DD * NA + tid];
    __syncthreads();

    int b = blockIdx.x * 8 + (tid >> 5);
    if (b >= B) return;
    int lane = tid & 31;

    float base[NA];
#pragma unroll
    for (int a = 0; a < NA; a++) base[a] = g_base[b * NA + a];
    float einv[18];
#pragma unroll
    for (int k = 0; k < 3; k++)
#pragma unroll
        for (int a = 0; a < NA; a++)
            einv[k * 6 + a] = g_einv[(k * B + b) * NA + a];

    float num[NA] = {0, 0, 0, 0, 0, 0}, den = 0.0f;

    for (int s = lane; s < NS; s += 32) {
        float p1 = 1.0f;
        float l[NA];
#pragma unroll
        for (int a = 0; a < NA; a++) l[a] = base[a];
#pragma unroll
        for (int k = 0; k < 3; k++) {
            int tb = ((k * NS + s) * B + b) * NA;
            const float2* tp = reinterpret_cast<const float2*>(g_tbuf + tb);
            float2 t01 = tp[0], t23 = tp[1], t45 = tp[2];
            float t[6] = {t01.x, t01.y, t23.x, t23.y, t45.x, t45.y};
            float vmin = 3.4e38f; int amin = 0;
#pragma unroll
            for (int a = 0; a < NA; a++) {
                float v = t[a] * einv[k * 6 + a];
                if (v < vmin) { vmin = v; amin = a; }   // strict < keeps first index (matches argmax tie rule)
            }
            p1 *= __ldg(&g_dist[(k * B + b) * NA + amin]);
#pragma unroll
            for (int a = 0; a < NA; a++) l[a] += W2s[(k * 6 + amin) * NA + a];
        }
        float m = l[0];
#pragma unroll
        for (int a = 1; a < NA; a++) m = fmaxf(m, l[a]);
        float e[NA], S = 0.0f;
#pragma unroll
        for (int a = 0; a < NA; a++) { e[a] = expf(l[a] - m); S += e[a]; }
        float w = p1 / S;
#pragma unroll
        for (int a = 0; a < NA; a++) num[a] = fmaf(w, e[a], num[a]);
        den += p1;
    }
#pragma unroll
    for (int off = 16; off; off >>= 1) {
#pragma unroll
        for (int a = 0; a < NA; a++)
            num[a] += __shfl_down_sync(0xffffffffu, num[a], off);
        den += __shfl_down_sync(0xffffffffu, den, off);
    }
    if (lane == 0) {
#pragma unroll
        for (int a = 0; a < NA; a++) out[b * NA + a] = num[a] / den;
    }
}

// ---------------- kernel 4: deterministic entropy reduction ----------------
__global__ void __launch_bounds__(1024) k4(float* __restrict__ out, int B, int out_size)
{
    __shared__ float sm[1024];
    int tid = threadIdx.x;
    float s = 0.0f;
    for (int i = tid; i < B; i += 1024) s += g_entpart[i];
    sm[tid] = s;
    __syncthreads();
    for (int off = 512; off; off >>= 1) {
        if (tid < off) sm[tid] += sm[tid + off];
        __syncthreads();
    }
    if (tid == 0 && out_size >= B * 24 + 1)
        out[B * 24] = sm[0] / (3.0f * (float)B);
}

// ---------------- launch ----------------
extern "C" void kernel_launch(void* const* d_in, const int* in_sizes, int n_in,
                              void* d_out, int out_size)
{
    const float* x    = (const float*)d_in[0];
    const float* Wopp = (const float*)d_in[1];
    const float* bopp = (const float*)d_in[2];
    const float* W    = (const float*)d_in[3];
    const float* bias = (const float*)d_in[4];
    float* out = (float*)d_out;

    int D = in_sizes[1] / (NOPP * NA);   // 512
    int B = in_sizes[0] / D;             // 4096
    if (B > BMAX) B = BMAX;
    int total = NOPP * NS * B * NA;      // 5,898,240 gumbel draws

    k1<<<(B + K1_ROWS - 1) / K1_ROWS, 768>>>(x, Wopp, bopp, W, bias, out, B, out_size);
    k_rng<<<((total / 2) + 255) / 256, 256>>>(total);
    k3<<<(B + 7) / 8, 256>>>(W, out, B);
    k4<<<1, 1024>>>(out, B, out_size);
}

// round 3
// speedup vs baseline: 1.2256x; 1.2256x over previous
#include <cuda_runtime.h>
#include <stdint.h>

#define NOPP 3
#define NS   80
#define NA   6
#define DD   512
#define BMAX 4096

// ---------------- device scratch (no allocations allowed) ----------------
__device__ float g_einv[NOPP * BMAX * NA];        // exp(-logits[k,b,a])
__device__ float g_dist[NOPP * BMAX * NA];        // softmax(logits)
__device__ float g_base[BMAX * NA];               // x@W[:512] + b  (agent base logits)
__device__ float g_entpart[BMAX];                 // sum_k entropy(k,b)

// ---------------- kernel 1: fused GEMM (x @ [W_opp|W[:512]]) + softmax/entropy ----------------
#define K1_ROWS 16
__global__ void __launch_bounds__(768) k1(
    const float* __restrict__ x, const float* __restrict__ Wopp,
    const float* __restrict__ bopp, const float* __restrict__ W,
    const float* __restrict__ bias, float* __restrict__ out,
    int B, int out_size)
{
    __shared__ float xs[K1_ROWS * DD];       // 32 KB
    __shared__ float vals[K1_ROWS][25];      // 24 outputs per row (+pad)
    __shared__ float entkb[K1_ROWS][3];

    int tid  = threadIdx.x;
    int warp = tid >> 5;       // 0..23 -> output column o
    int lane = tid & 31;
    int b0   = blockIdx.x * K1_ROWS;

    // stage x rows
    for (int i = tid; i < K1_ROWS * DD; i += 768) {
        int r = i / DD;
        xs[i] = (b0 + r < B) ? x[(size_t)(b0 + r) * DD + (i % DD)] : 0.0f;
    }

    // each warp owns one output column o; W column in registers
    float wreg[16];
    int o = warp;
    if (o < 18) {
        int k = o / 6, a = o % 6;
#pragma unroll
        for (int j = 0; j < 16; j++)
            wreg[j] = Wopp[((size_t)k * DD + (lane + 32 * j)) * NA + a];
    } else {
        int a = o - 18;
#pragma unroll
        for (int j = 0; j < 16; j++)
            wreg[j] = W[(size_t)(lane + 32 * j) * NA + a];
    }
    __syncthreads();

    for (int r = 0; r < K1_ROWS; r++) {
        const float* xr = xs + r * DD;
        float acc = 0.0f;
#pragma unroll
        for (int j = 0; j < 16; j++)
            acc = fmaf(xr[lane + 32 * j], wreg[j], acc);
#pragma unroll
        for (int off = 16; off; off >>= 1)
            acc += __shfl_down_sync(0xffffffffu, acc, off);
        if (lane == 0) vals[r][o] = acc;
    }
    __syncthreads();

    // post-process: 48 (row, opponent) softmax tasks + 96 base tasks (accurate math:
    // dist/entropy feed the output directly)
    if (tid < K1_ROWS * 3) {
        int r = tid / 3, k = tid % 3;
        int b = b0 + r;
        if (b < B) {
            float l[NA], m = -1e30f;
#pragma unroll
            for (int a = 0; a < NA; a++) {
                l[a] = vals[r][k * 6 + a] + bopp[k * 6 + a];
                m = fmaxf(m, l[a]);
            }
            float e[NA], S = 0.0f;
#pragma unroll
            for (int a = 0; a < NA; a++) { e[a] = expf(l[a] - m); S += e[a]; }
            float logS = logf(S);
            float ent = 0.0f;
            int distoff = B * NA + (k * B + b) * NA;
#pragma unroll
            for (int a = 0; a < NA; a++) {
                float d = e[a] / S;
                g_dist[(k * B + b) * NA + a] = d;
                g_einv[(k * B + b) * NA + a] = expf(-l[a]);
                float lp = (l[a] - m) - logS;
                ent -= d * lp;
                if (out_size >= B * 24) out[distoff + a] = d;
            }
            entkb[r][k] = ent;
        } else entkb[r][k] = 0.0f;
    } else if (tid < K1_ROWS * 3 + K1_ROWS * 6) {
        int t2 = tid - K1_ROWS * 3;
        int r = t2 / 6, a = t2 % 6;
        int b = b0 + r;
        if (b < B) g_base[b * NA + a] = vals[r][18 + a] + bias[a];
    }
    __syncthreads();
    if (tid < K1_ROWS && b0 + tid < B)
        g_entpart[b0 + tid] = entkb[tid][0] + entkb[tid][1] + entkb[tid][2];
}

// ---------------- threefry2x32, key = (0, 42), counter = (hi=0, lo=i) ----------------
// jax partitionable 32-bit stream: output = x0_final ^ x1_final
__device__ __forceinline__ uint32_t tf_fold(uint32_t c1)
{
    const uint32_t KS1 = 42u;
    const uint32_t KS2 = 0x1BD11BDAu ^ 42u;   // ks0 = 0
    uint32_t x0 = 0u, x1 = c1 + KS1;
#define TFR(r) { x0 += x1; x1 = __funnelshift_l(x1, x1, (r)); x1 ^= x0; }
    TFR(13) TFR(15) TFR(26) TFR(6)
    x0 += KS1; x1 += KS2 + 1u;
    TFR(17) TFR(29) TFR(16) TFR(24)
    x0 += KS2; x1 += 2u;
    TFR(13) TFR(15) TFR(26) TFR(6)
    x1 += KS1 + 3u;
    TFR(17) TFR(29) TFR(16) TFR(24)
    x0 += KS1; x1 += KS2 + 4u;
    TFR(13) TFR(15) TFR(26) TFR(6)
    x0 += KS2; x1 += 5u;
#undef TFR
    return x0 ^ x1;
}

// t = -log(u), u = (bitcast(bits>>9 | 0x3f800000) - 1) + tiny.
// Fast log: only feeds the argmin comparison (monotone), not the output values.
__device__ __forceinline__ float bits_to_t_fast(uint32_t bits)
{
    float f = __uint_as_float((bits >> 9) | 0x3f800000u) - 1.0f;
    return -__logf(f + 1.17549435e-38f);
}

// ---------------- kernel 2: fused RNG + sampling + weighted agent softmax + entropy ----------
__global__ void __launch_bounds__(256) k3f(const float* __restrict__ W,
                                           float* __restrict__ out, int B, int out_size)
{
    __shared__ float W2s[18 * NA];
    __shared__ float esm[256];
    int tid = threadIdx.x;
    if (tid < 18 * NA) W2s[tid] = W[DD * NA + tid];

    // block 0 additionally reduces the entropy partials (k1 completed: stream order)
    if (blockIdx.x == 0) {
        float s = 0.0f;
        for (int i = tid; i < B; i += 256) s += g_entpart[i];
        esm[tid] = s;
        __syncthreads();
        for (int off = 128; off; off >>= 1) {
            if (tid < off) esm[tid] += esm[tid + off];
            __syncthreads();
        }
        if (tid == 0 && out_size >= B * 24 + 1)
            out[B * 24] = esm[0] / (3.0f * (float)B);
    }
    __syncthreads();

    int warp = tid >> 5;
    int lane = tid & 31;
    int b = blockIdx.x * 8 + warp;
    if (b >= B) return;

    float base[NA], einv[18], dist[18];
#pragma unroll
    for (int a = 0; a < NA; a++) base[a] = g_base[b * NA + a];
#pragma unroll
    for (int k = 0; k < 3; k++)
#pragma unroll
        for (int a = 0; a < NA; a++) {
            einv[k * 6 + a] = g_einv[(k * B + b) * NA + a];
            dist[k * 6 + a] = g_dist[(k * B + b) * NA + a];
        }

    float num[NA] = {0, 0, 0, 0, 0, 0}, den = 0.0f;

    for (int s = lane; s < NS; s += 32) {
        float p1 = 1.0f;
        float l[NA];
#pragma unroll
        for (int a = 0; a < NA; a++) l[a] = base[a];
#pragma unroll
        for (int k = 0; k < 3; k++) {
            uint32_t c0 = (uint32_t)(((k * NS + s) * B + b) * NA);
            float vmin = 3.4e38f, dsel = 0.0f;
            int amin = 0;
#pragma unroll
            for (int a = 0; a < NA; a++) {      // 6 independent hash chains -> ILP
                float t = bits_to_t_fast(tf_fold(c0 + (uint32_t)a));
                float v = t * einv[k * 6 + a];
                if (v < vmin) { vmin = v; amin = a; dsel = dist[k * 6 + a]; }
            }
            p1 *= dsel;
#pragma unroll
            for (int a = 0; a < NA; a++) l[a] += W2s[(k * 6 + amin) * NA + a];
        }
        float m = l[0];
#pragma unroll
        for (int a = 1; a < NA; a++) m = fmaxf(m, l[a]);
        float e[NA], S = 0.0f;
#pragma unroll
        for (int a = 0; a < NA; a++) { e[a] = __expf(l[a] - m); S += e[a]; }
        float w = p1 / S;
#pragma unroll
        for (int a = 0; a < NA; a++) num[a] = fmaf(w, e[a], num[a]);
        den += p1;
    }
#pragma unroll
    for (int off = 16; off; off >>= 1) {
#pragma unroll
        for (int a = 0; a < NA; a++)
            num[a] += __shfl_down_sync(0xffffffffu, num[a], off);
        den += __shfl_down_sync(0xffffffffu, den, off);
    }
    if (lane == 0) {
        float inv = 1.0f / den;
#pragma unroll
        for (int a = 0; a < NA; a++) out[b * NA + a] = num[a] * inv;
    }
}

// ---------------- launch ----------------
extern "C" void kernel_launch(void* const* d_in, const int* in_sizes, int n_in,
                              void* d_out, int out_size)
{
    const float* x    = (const float*)d_in[0];
    const float* Wopp = (const float*)d_in[1];
    const float* bopp = (const float*)d_in[2];
    const float* W    = (const float*)d_in[3];
    const float* bias = (const float*)d_in[4];
    float* out = (float*)d_out;

    int D = in_sizes[1] / (NOPP * NA);   // 512
    int B = in_sizes[0] / D;             // 4096
    if (B > BMAX) B = BMAX;

    k1<<<(B + K1_ROWS - 1) / K1_ROWS, 768>>>(x, Wopp, bopp, W, bias, out, B, out_size);
    k3f<<<(B + 7) / 8, 256>>>(W, out, B, out_size);
}

// round 4
// speedup vs baseline: 1.4843x; 1.2111x over previous
#include <cuda_runtime.h>
#include <stdint.h>

#define NOPP 3
#define NS   80
#define NA   6
#define DD   512
#define ROWS 16   // batch rows per block

// entropy accumulator: fixed-point 2^41, reset by the last block each launch
__device__ unsigned long long g_entacc;
__device__ unsigned int g_ticket;

// ---------------- threefry2x32, key=(0,42), counter=(0,i); out = x0^x1 ----------------
__device__ __forceinline__ uint32_t tf_fold(uint32_t c1)
{
    const uint32_t KS1 = 42u;
    const uint32_t KS2 = 0x1BD11BDAu ^ 42u;   // ks0 = 0
    uint32_t x0 = 0u, x1 = c1 + KS1;
#define TFR(r) { x0 += x1; x1 = __funnelshift_l(x1, x1, (r)); x1 ^= x0; }
    TFR(13) TFR(15) TFR(26) TFR(6)
    x0 += KS1; x1 += KS2 + 1u;
    TFR(17) TFR(29) TFR(16) TFR(24)
    x0 += KS2; x1 += 2u;
    TFR(13) TFR(15) TFR(26) TFR(6)
    x1 += KS1 + 3u;
    TFR(17) TFR(29) TFR(16) TFR(24)
    x0 += KS1; x1 += KS2 + 4u;
    TFR(13) TFR(15) TFR(26) TFR(6)
    x0 += KS2; x1 += 5u;
#undef TFR
    return x0 ^ x1;
}

// t = -log(u); fast log feeds only the (monotone) argmin comparison
__device__ __forceinline__ float bits_to_t_fast(uint32_t bits)
{
    float f = __uint_as_float((bits >> 9) | 0x3f800000u) - 1.0f;
    return -__logf(f + 1.17549435e-38f);
}

__global__ void __launch_bounds__(256) kfused(
    const float* __restrict__ x, const float* __restrict__ Wopp,
    const float* __restrict__ bopp, const float* __restrict__ W,
    const float* __restrict__ bias, float* __restrict__ out,
    int B, int out_size)
{
    __shared__ float xs[ROWS * DD];          // 32 KB
    __shared__ float vals[ROWS][25];
    __shared__ float einv_s[ROWS][20];
    __shared__ float dist_s[ROWS][20];
    __shared__ float base_s[ROWS][8];
    __shared__ float W2s[18 * 8];            // padded pitch 8
    __shared__ float entkb[ROWS * 3];

    int tid  = threadIdx.x;
    int warp = tid >> 5;
    int lane = tid & 31;
    int b0   = blockIdx.x * ROWS;

    // W tail (rows 512..529) into shared, padded
    if (tid < 18 * NA) W2s[(tid / 6) * 8 + (tid % 6)] = W[DD * NA + tid];

    // ---- stage x rows ----
    if (b0 + ROWS <= B) {
        const float4* x4 = reinterpret_cast<const float4*>(x + (size_t)b0 * DD);
        float4* xs4 = reinterpret_cast<float4*>(xs);
        for (int i = tid; i < ROWS * DD / 4; i += 256) xs4[i] = x4[i];
    } else {
        for (int i = tid; i < ROWS * DD; i += 256) {
            int r = i / DD;
            xs[i] = (b0 + r < B) ? x[(size_t)(b0 + r) * DD + (i % DD)] : 0.0f;
        }
    }

    // ---- per-warp weight columns 3w..3w+2 in registers ----
    float w0[16], w1[16], w2[16];
    {
        int c = 3 * warp;
        const float* s0 = (c + 0 < 18) ? (Wopp + (size_t)((c + 0) / 6) * DD * NA + ((c + 0) % 6))
                                       : (W + (c + 0 - 18));
        const float* s1 = (c + 1 < 18) ? (Wopp + (size_t)((c + 1) / 6) * DD * NA + ((c + 1) % 6))
                                       : (W + (c + 1 - 18));
        const float* s2 = (c + 2 < 18) ? (Wopp + (size_t)((c + 2) / 6) * DD * NA + ((c + 2) % 6))
                                       : (W + (c + 2 - 18));
#pragma unroll
        for (int j = 0; j < 16; j++) {
            size_t idx = (size_t)(lane + 32 * j) * NA;
            w0[j] = s0[idx]; w1[j] = s1[idx]; w2[j] = s2[idx];
        }
    }
    __syncthreads();

    // ---- GEMM: 16 rows x 24 cols ----
    for (int r = 0; r < ROWS; r++) {
        const float* xr = xs + r * DD + lane;
        float a0 = 0.f, a1 = 0.f, a2 = 0.f;
#pragma unroll
        for (int j = 0; j < 16; j++) {
            float xv = xr[32 * j];
            a0 = fmaf(xv, w0[j], a0);
            a1 = fmaf(xv, w1[j], a1);
            a2 = fmaf(xv, w2[j], a2);
        }
#pragma unroll
        for (int off = 16; off; off >>= 1) {
            a0 += __shfl_down_sync(0xffffffffu, a0, off);
            a1 += __shfl_down_sync(0xffffffffu, a1, off);
            a2 += __shfl_down_sync(0xffffffffu, a2, off);
        }
        if (lane == 0) {
            vals[r][3 * warp + 0] = a0;
            vals[r][3 * warp + 1] = a1;
            vals[r][3 * warp + 2] = a2;
        }
    }
    __syncthreads();

    // ---- postprocess: softmax/einv/dist/entropy + agent base logits ----
    if (tid < ROWS * 3) {
        int r = tid / 3, k = tid % 3, b = b0 + r;
        if (b < B) {
            float l[NA], m = -1e30f;
#pragma unroll
            for (int a = 0; a < NA; a++) {
                l[a] = vals[r][k * 6 + a] + bopp[k * 6 + a];
                m = fmaxf(m, l[a]);
            }
            float e[NA], S = 0.0f;
#pragma unroll
            for (int a = 0; a < NA; a++) { e[a] = expf(l[a] - m); S += e[a]; }
            float logS = logf(S);
            float ent = 0.0f;
            size_t distoff = (size_t)B * NA + ((size_t)k * B + b) * NA;
#pragma unroll
            for (int a = 0; a < NA; a++) {
                float d = e[a] / S;
                dist_s[r][k * 6 + a] = d;
                einv_s[r][k * 6 + a] = expf(-l[a]);
                ent -= d * ((l[a] - m) - logS);
                if (out_size >= B * 24) out[distoff + a] = d;
            }
            entkb[tid] = ent;
        } else entkb[tid] = 0.0f;
    } else if (tid < ROWS * 3 + ROWS * 6) {
        int t2 = tid - ROWS * 3;
        int r = t2 / 6, a = t2 % 6, b = b0 + r;
        if (b < B) base_s[r][a] = vals[r][18 + a] + bias[a];
    }
    __syncthreads();

    // ---- entropy: fixed-point atomic + last-block ticket (deterministic) ----
    if (tid == 0) {
        float part = 0.0f;
        for (int i = 0; i < ROWS * 3; i++) part += entkb[i];
        unsigned long long q =
            (unsigned long long)__double2ll_rn((double)part * 2199023255552.0); // 2^41
        atomicAdd(&g_entacc, q);
        __threadfence();
        unsigned int old = atomicAdd(&g_ticket, 1u);
        if (old == gridDim.x - 1) {
            unsigned long long tot = atomicExch(&g_entacc, 0ull);
            atomicExch(&g_ticket, 0u);
            if (out_size >= B * 24 + 1)
                out[(size_t)B * 24] =
                    (float)((double)tot * (1.0 / 2199023255552.0) / (3.0 * (double)B));
        }
    }

    // ---- sampling: 16 lanes per batch row, 2 rows per warp, 5 samples/lane ----
    int h  = lane >> 4;
    int sl = lane & 15;
    int rl = warp * 2 + h;
    int b  = b0 + rl;
    unsigned int smask = __ballot_sync(0xffffffffu, b < B);
    if (b >= B) return;

    float base[NA], einv[18];
#pragma unroll
    for (int a = 0; a < NA; a++) base[a] = base_s[rl][a];
#pragma unroll
    for (int i = 0; i < 18; i++) einv[i] = einv_s[rl][i];

    float num[NA] = {0, 0, 0, 0, 0, 0}, den = 0.0f;

    for (int s = sl; s < NS; s += 16) {
        float p1 = 1.0f, l[NA];
#pragma unroll
        for (int a = 0; a < NA; a++) l[a] = base[a];
#pragma unroll
        for (int k = 0; k < 3; k++) {
            uint32_t c0 = (uint32_t)(((k * NS + s) * B + b) * NA);
            uint32_t mp = 0xFFFFFFFFu;
#pragma unroll
            for (int a = 0; a < NA; a++) {      // 6 independent hash chains -> ILP
                float t = bits_to_t_fast(tf_fold(c0 + (uint32_t)a));
                float v = t * einv[k * 6 + a];
                uint32_t pv = (__float_as_uint(v) & 0xFFFFFFF8u) | (uint32_t)a;
                mp = (mp < pv) ? mp : pv;       // umin keeps first index on ties
            }
            int amin = (int)(mp & 7u);
            p1 *= dist_s[rl][k * 6 + amin];
#pragma unroll
            for (int a = 0; a < NA; a++) l[a] += W2s[(k * 6 + amin) * 8 + a];
        }
        float m = l[0];
#pragma unroll
        for (int a = 1; a < NA; a++) m = fmaxf(m, l[a]);
        float e[NA], S = 0.0f;
#pragma unroll
        for (int a = 0; a < NA; a++) { e[a] = __expf(l[a] - m); S += e[a]; }
        float w = p1 / S;
#pragma unroll
        for (int a = 0; a < NA; a++) num[a] = fmaf(w, e[a], num[a]);
        den += p1;
    }
#pragma unroll
    for (int off = 8; off; off >>= 1) {
#pragma unroll
        for (int a = 0; a < NA; a++)
            num[a] += __shfl_down_sync(smask, num[a], off, 16);
        den += __shfl_down_sync(smask, den, off, 16);
    }
    if (sl == 0) {
        float inv = 1.0f / den;
#pragma unroll
        for (int a = 0; a < NA; a++) out[(size_t)b * NA + a] = num[a] * inv;
    }
}

// ---------------- launch ----------------
extern "C" void kernel_launch(void* const* d_in, const int* in_sizes, int n_in,
                              void* d_out, int out_size)
{
    const float* x    = (const float*)d_in[0];
    const float* Wopp = (const float*)d_in[1];
    const float* bopp = (const float*)d_in[2];
    const float* W    = (const float*)d_in[3];
    const float* bias = (const float*)d_in[4];
    float* out = (float*)d_out;

    int D = in_sizes[1] / (NOPP * NA);   // 512
    int B = in_sizes[0] / D;             // 4096

    int grid = (B + ROWS - 1) / ROWS;
    kfused<<<grid, 256>>>(x, Wopp, bopp, W, bias, out, B, out_size);
}